// round 12
// baseline (speedup 1.0000x reference)
#include <cuda_runtime.h>
#include <cuda_bf16.h>
#include <stdint.h>

#define NTOK   16384
#define DIM    2048
#define NE     64
#define KTOP   8
#define ALPHA_C 0.001f

#define TM     128                 // tokens per CTA
#define NT     512                 // 16 warps: 4 m-tiles x 2 n-tiles x 2 k-halves
#define KC     64                  // k per chunk
#define NBLK   (NTOK / TM)         // 128 CTAs -> 1 per SM, uniform
#define NCH    (DIM / KC)          // 32 chunks
#define TAU    1e-4f               // near-tie fallback threshold (logit gap)

// smem tiles: bf16, padded pitch 72 bf16 = 144B (ldmatrix rows -> banks 0,4,..,28)
#define APB    144
#define ABYTES (128 * APB)         // 18432 per term
#define BBYTES (64 * APB)          // 9216 per term
#define PERBUF (2 * ABYTES + 2 * BBYTES)   // 55296
#define AOFF(b, t) ((b) * PERBUF + (t) * ABYTES)
#define BOFF(b, t) ((b) * PERBUF + 2 * ABYTES + (t) * BBYTES)
#define DYN_BYTES (2 * PERBUF + 1024)

__device__ float g_cnt_part[NBLK][NE];
__device__ float g_prob_part[NBLK][NE];
__device__ unsigned int g_sync = 0;   // atomicInc wraps each launch -> graph-replay safe

static __device__ __forceinline__ uint32_t smem_u32(const void* p) {
    uint32_t a;
    asm("{ .reg .u64 t; cvta.to.shared.u64 t, %1; cvt.u32.u64 %0, t; }" : "=r"(a) : "l"(p));
    return a;
}

// baseline-PTX tensor ops (sm_75/80+, valid for plain sm_103 target)
#define LDSM4(r, a) \
    asm volatile("ldmatrix.sync.aligned.m8n8.x4.shared.b16 {%0,%1,%2,%3}, [%4];" \
        : "=r"((r)[0]), "=r"((r)[1]), "=r"((r)[2]), "=r"((r)[3]) : "r"(a))

#define MMA(d, a, b) \
    asm volatile("mma.sync.aligned.m16n8k16.row.col.f32.bf16.bf16.f32 " \
        "{%0,%1,%2,%3}, {%4,%5,%6,%7}, {%8,%9}, {%0,%1,%2,%3};" \
        : "+f"((d)[0]), "+f"((d)[1]), "+f"((d)[2]), "+f"((d)[3]) \
        : "r"((a)[0]), "r"((a)[1]), "r"((a)[2]), "r"((a)[3]), "r"((b)[0]), "r"((b)[1]))

// fp32x4 -> bf16 hi (4) + bf16 lo (4), pairwise cvt (k order preserved)
static __device__ __forceinline__ void split4(float4 v, uint2& hi, uint2& lo) {
    __nv_bfloat162 h0 = __float22bfloat162_rn(make_float2(v.x, v.y));
    __nv_bfloat162 h1 = __float22bfloat162_rn(make_float2(v.z, v.w));
    float2 f0 = __bfloat1622float2(h0);
    float2 f1 = __bfloat1622float2(h1);
    __nv_bfloat162 l0 = __float22bfloat162_rn(make_float2(v.x - f0.x, v.y - f0.y));
    __nv_bfloat162 l1 = __float22bfloat162_rn(make_float2(v.z - f1.x, v.w - f1.y));
    hi.x = *reinterpret_cast<uint32_t*>(&h0);
    hi.y = *reinterpret_cast<uint32_t*>(&h1);
    lo.x = *reinterpret_cast<uint32_t*>(&l0);
    lo.y = *reinterpret_cast<uint32_t*>(&l1);
}

// ---- chunk stages (NT=512: A 4 f4/thread, B 2 f4/thread) ----
static __device__ __forceinline__ void ldg_chunk(const float* Hb, const float* W, int c, int tid,
                                                 float4 (&ha)[4], float4 (&wa)[2]) {
    const float* hp = Hb + c * KC;
#pragma unroll
    for (int g = 0; g < 4; g++) {
        int flat = tid + 512 * g, row = flat >> 4, f4 = flat & 15;
        ha[g] = *(const float4*)(hp + (size_t)row * DIM + f4 * 4);
    }
    const float* wp = W + c * KC;
#pragma unroll
    for (int g = 0; g < 2; g++) {
        int flat = tid + 512 * g, row = flat >> 4, f4 = flat & 15;
        wa[g] = *(const float4*)(wp + (size_t)row * DIM + f4 * 4);
    }
}
static __device__ __forceinline__ void sts_chunk(char* base, int buf, int tid,
                                                 const float4 (&ha)[4], const float4 (&wa)[2]) {
#pragma unroll
    for (int g = 0; g < 4; g++) {
        int flat = tid + 512 * g, row = flat >> 4, f4 = flat & 15;
        int off = row * APB + f4 * 8;
        uint2 hi, lo; split4(ha[g], hi, lo);
        *(uint2*)(base + AOFF(buf, 0) + off) = hi;
        *(uint2*)(base + AOFF(buf, 1) + off) = lo;
    }
#pragma unroll
    for (int g = 0; g < 2; g++) {
        int flat = tid + 512 * g, row = flat >> 4, f4 = flat & 15;
        int off = row * APB + f4 * 8;
        uint2 hi, lo; split4(wa[g], hi, lo);
        *(uint2*)(base + BOFF(buf, 0) + off) = hi;
        *(uint2*)(base + BOFF(buf, 1) + off) = lo;
    }
}

// warp tile: m32 (rows (wid&3)*32) x n32 (cols ((wid>>2)&1)*32), k-half (wid>>3).
// Per k16-step: 8 LDSM4, 24 HMMA (ratio 3). Per-acc term order hh, hl, lh.
static __device__ __forceinline__ void compute_chunk(uint32_t dynb32, int buf, int wid, int lane,
                                                     float (&acc)[2][4][4]) {
    const uint32_t aHi = dynb32 + AOFF(buf, 0), aLo = dynb32 + AOFF(buf, 1);
    const uint32_t bHi = dynb32 + BOFF(buf, 0), bLo = dynb32 + BOFF(buf, 1);
    const int mrow = (wid & 3) * 32;
    const int ncol = ((wid >> 2) & 1) * 32;
    const int kh   = wid >> 3;
    const uint32_t aR0 = (uint32_t)((mrow + (lane & 15)) * APB + (lane >> 4) * 16);
    const uint32_t aR1 = aR0 + (uint32_t)(16 * APB);
    const uint32_t bR0 = (uint32_t)((ncol + (lane & 7) + ((lane >> 4) & 1) * 8) * APB +
                                    ((lane >> 3) & 1) * 16);
#pragma unroll
    for (int ss = 0; ss < 2; ss++) {
        const uint32_t so = (uint32_t)((kh * 2 + ss) * 32);
        uint32_t ah0[4], ah1[4], al0[4], al1[4], bh[2][4], bl[2][4];
        LDSM4(ah0, aHi + aR0 + so);
        LDSM4(ah1, aHi + aR1 + so);
        LDSM4(al0, aLo + aR0 + so);
        LDSM4(al1, aLo + aR1 + so);
        LDSM4(bh[0], bHi + bR0 + so);
        LDSM4(bh[1], bHi + bR0 + (uint32_t)(16 * APB) + so);
        LDSM4(bl[0], bLo + bR0 + so);
        LDSM4(bl[1], bLo + bR0 + (uint32_t)(16 * APB) + so);
        // term-major; same-acc revisit distance 8
#pragma unroll
        for (int jp = 0; jp < 2; jp++) {               // hh
            MMA(acc[0][2 * jp],     ah0, bh[jp]);
            MMA(acc[0][2 * jp + 1], ah0, bh[jp] + 2);
            MMA(acc[1][2 * jp],     ah1, bh[jp]);
            MMA(acc[1][2 * jp + 1], ah1, bh[jp] + 2);
        }
#pragma unroll
        for (int jp = 0; jp < 2; jp++) {               // hl
            MMA(acc[0][2 * jp],     ah0, bl[jp]);
            MMA(acc[0][2 * jp + 1], ah0, bl[jp] + 2);
            MMA(acc[1][2 * jp],     ah1, bl[jp]);
            MMA(acc[1][2 * jp + 1], ah1, bl[jp] + 2);
        }
#pragma unroll
        for (int jp = 0; jp < 2; jp++) {               // lh
            MMA(acc[0][2 * jp],     al0, bh[jp]);
            MMA(acc[0][2 * jp + 1], al0, bh[jp] + 2);
            MMA(acc[1][2 * jp],     al1, bh[jp]);
            MMA(acc[1][2 * jp + 1], al1, bh[jp] + 2);
        }
    }
}

__global__ __launch_bounds__(NT, 1)
void gate_kernel(const float* __restrict__ H, const float* __restrict__ W,
                 float* __restrict__ out, int out_size)
{
    extern __shared__ char dynsm[];
    __shared__ float logits[TM][NE + 1];
    __shared__ float rinv[TM];
    __shared__ float sm_cnt[NE];
    __shared__ float pr[8][NE];
    __shared__ float rc[8][NE], rp[8][NE];
    __shared__ unsigned int is_last;
    __shared__ int fb_cnt;
    __shared__ int fb_list[TM];

    const int tid  = threadIdx.x;
    const int blk  = blockIdx.x;
    const int wid  = tid >> 5;
    const int lane = tid & 31;
    char* base = (char*)((((uintptr_t)dynsm) + 1023) & ~(uintptr_t)1023);
    const uint32_t dynb32 = smem_u32(base);

    if (tid == 0) fb_cnt = 0;
    if (tid < NE) sm_cnt[tid] = 0.f;

    float acc[2][4][4];
#pragma unroll
    for (int m = 0; m < 2; m++)
#pragma unroll
        for (int j = 0; j < 4; j++)
#pragma unroll
            for (int q = 0; q < 4; q++) acc[m][j][q] = 0.f;

    const float* Hb = H + (size_t)blk * TM * DIM;

    // -------- GEMM: 3-term split-bf16 via HMMA, k-split across warp groups --------
    float4 ha[4]; float4 wa[2];
    ldg_chunk(Hb, W, 0, tid, ha, wa);
    sts_chunk(base, 0, tid, ha, wa);
    for (int c = 0; c < NCH; c++) {
        const bool more = (c + 1 < NCH);
        if (more) ldg_chunk(Hb, W, c + 1, tid, ha, wa);
        __syncthreads();
        compute_chunk(dynb32, c & 1, wid, lane, acc);
        if (more) sts_chunk(base, (c + 1) & 1, tid, ha, wa);
    }

    // -------- k-half partials -> logits smem (write then add; deterministic) --------
    {
        const int mrow = (wid & 3) * 32;
        const int ncol = ((wid >> 2) & 1) * 32;
        const int kh   = wid >> 3;
        const int r  = lane >> 2;
        const int cb = (lane & 3) * 2;
        if (kh == 0) {
#pragma unroll
            for (int m = 0; m < 2; m++)
#pragma unroll
                for (int j = 0; j < 4; j++) {
                    logits[mrow + m * 16 + r][ncol + cb + j * 8]         = acc[m][j][0];
                    logits[mrow + m * 16 + r][ncol + cb + j * 8 + 1]     = acc[m][j][1];
                    logits[mrow + m * 16 + r + 8][ncol + cb + j * 8]     = acc[m][j][2];
                    logits[mrow + m * 16 + r + 8][ncol + cb + j * 8 + 1] = acc[m][j][3];
                }
        }
        __syncthreads();
        if (kh == 1) {
#pragma unroll
            for (int m = 0; m < 2; m++)
#pragma unroll
                for (int j = 0; j < 4; j++) {
                    logits[mrow + m * 16 + r][ncol + cb + j * 8]         += acc[m][j][0];
                    logits[mrow + m * 16 + r][ncol + cb + j * 8 + 1]     += acc[m][j][1];
                    logits[mrow + m * 16 + r + 8][ncol + cb + j * 8]     += acc[m][j][2];
                    logits[mrow + m * 16 + r + 8][ncol + cb + j * 8 + 1] += acc[m][j][3];
                }
        }
    }
    __syncthreads();

    // -------- near-tie detection: any adjacent gap in top-9 below TAU --------
    if (tid < TM) {
        float v[9];
#pragma unroll
        for (int j = 0; j < 9; j++) v[j] = -1e30f;
        for (int e = 0; e < NE; e++) {
            float nv = logits[tid][e];
#pragma unroll
            for (int j = 0; j < 9; j++) {
                if (nv > v[j]) { float t = v[j]; v[j] = nv; nv = t; }
            }
        }
        float mingap = 1e30f;
#pragma unroll
        for (int j = 0; j < 8; j++) mingap = fminf(mingap, v[j] - v[j + 1]);
        if (mingap < TAU) {
            int ix = atomicAdd(&fb_cnt, 1);
            fb_list[ix] = tid;
        }
    }
    __syncthreads();

    // -------- exact fp32 sequential-k fallback (R0 bit-exact), 8 tokens/pass --------
    {
        const int nfb = fb_cnt;
        for (int f0 = 0; f0 < nfb; f0 += 8) {
            const int fi = f0 + (tid >> 6);
            if (fi < nfb) {
                const int t = fb_list[fi];
                const int e = tid & 63;
                const float* hr = H + (size_t)(blk * TM + t) * DIM;
                const float* wr = W + (size_t)e * DIM;
                float a = 0.f;
                for (int k = 0; k < DIM; k += 4) {
                    float4 hv = *(const float4*)(hr + k);
                    float4 wv = *(const float4*)(wr + k);
                    a = fmaf(hv.x, wv.x, a);
                    a = fmaf(hv.y, wv.y, a);
                    a = fmaf(hv.z, wv.z, a);
                    a = fmaf(hv.w, wv.w, a);
                }
                logits[t][e] = a;
            }
        }
    }
    __syncthreads();

    // -------- per-token softmax + top-8 (proven R0 pipeline) --------
    if (tid < TM) {
        float m = -1e30f;
        for (int e = 0; e < NE; e++) m = fmaxf(m, logits[tid][e]);

        float s = 0.f;
        float val[KTOP]; int idx[KTOP];
#pragma unroll
        for (int j = 0; j < KTOP; j++) { val[j] = -1.f; idx[j] = 0; }
        for (int e = 0; e < NE; e++) {
            float ex = __expf(logits[tid][e] - m);
            logits[tid][e] = ex;   // stash exp for mean-prob pass
            s += ex;
            float nv = ex; int ni = e;
#pragma unroll
            for (int j = 0; j < KTOP; j++) {
                if (nv > val[j]) {
                    float tv = val[j]; val[j] = nv; nv = tv;
                    int   ti = idx[j]; idx[j] = ni; ni = ti;
                }
            }
        }
        rinv[tid] = 1.f / s;

        float ts = 0.f;
#pragma unroll
        for (int j = 0; j < KTOP; j++) ts += val[j];
        const float tinv = 1.f / ts;

        const int gt = blk * TM + tid;
        float* ow = out + (size_t)gt * KTOP;
        float* oi = out + (size_t)NTOK * KTOP + (size_t)gt * KTOP;
#pragma unroll
        for (int j = 0; j < KTOP; j++) {
            ow[j] = val[j] * tinv;
            oi[j] = (float)idx[j];
            atomicAdd(&sm_cnt[idx[j]], 1.f);  // integer counts: order-exact
        }
    }
    __syncthreads();

    // -------- per-block mean-prob partial (8 parts x 16 tokens) --------
    {
        const int e = tid & 63;
        const int p = tid >> 6;
        float sacc = 0.f;
        for (int t = p * 16; t < p * 16 + 16; t++)
            sacc += logits[t][e] * rinv[t];
        pr[p][e] = sacc;
    }
    __syncthreads();
    if (tid < NE) {
        float s = 0.f;
#pragma unroll
        for (int p = 0; p < 8; p++) s += pr[p][tid];
        g_prob_part[blk][tid] = s;
        g_cnt_part[blk][tid]  = sm_cnt[tid];
    }

    // -------- last block finalizes the aux loss --------
    __threadfence();
    if (tid == 0)
        is_last = (atomicInc(&g_sync, NBLK - 1) == NBLK - 1);
    __syncthreads();
    if (is_last) {
        const int e = tid & 63;
        const int p = tid >> 6;       // 8 parts x 16 blocks, fixed order
        float c = 0.f, pm = 0.f;
        for (int b = p * 16; b < p * 16 + 16; b++) {
            c  += g_cnt_part[b][e];
            pm += g_prob_part[b][e];
        }
        rc[p][e] = c; rp[p][e] = pm;
        __syncthreads();
        if (tid == 0) {
            float s = 0.f;
            for (int e2 = 0; e2 < NE; e2++) {
                float C = 0.f, P = 0.f;
#pragma unroll
                for (int p2 = 0; p2 < 8; p2++) { C += rc[p2][e2]; P += rp[p2][e2]; }
                s += (C / (float)(NTOK * KTOP)) * (P / (float)NTOK);
            }
            const int pos = NTOK * KTOP * 2;
            if (pos < out_size) out[pos] = ALPHA_C * (float)NE * s;
        }
    }
}

extern "C" void kernel_launch(void* const* d_in, const int* in_sizes, int n_in,
                              void* d_out, int out_size)
{
    const float* H = (const float*)d_in[0];   // hidden_states (16384, 2048) fp32
    const float* W = (const float*)d_in[1];   // weight (64, 2048) fp32
    float* out = (float*)d_out;

    cudaFuncSetAttribute(gate_kernel, cudaFuncAttributeMaxDynamicSharedMemorySize, DYN_BYTES);
    gate_kernel<<<NBLK, NT, DYN_BYTES>>>(H, W, out, out_size);
}

// round 13
// speedup vs baseline: 1.2810x; 1.2810x over previous
#include <cuda_runtime.h>
#include <cuda_bf16.h>
#include <stdint.h>

#define NTOK   16384
#define DIM    2048
#define NE     64
#define KTOP   8
#define ALPHA_C 0.001f

#define TM     64                  // tokens per CTA
#define NT     256                 // 8 warps: 2 m-tiles x 2 n-tiles x 2 k-halves
#define KC     64                  // k per chunk
#define NBLK   (NTOK / TM)         // 256 CTAs -> 2 per SM
#define NCH    (DIM / KC)          // 32 chunks
#define TAU    1e-4f               // near-tie fallback threshold (logit gap)

// smem tiles: bf16, padded pitch 72 bf16 = 144B (ldmatrix rows -> banks 0,4,..,28)
#define APB    144
#define TBYTES (64 * APB)          // 9216 per (tile,term)
#define PERBUF (4 * TBYTES)        // A-hi, A-lo, B-hi, B-lo = 36864
#define AOFF(b, t) ((b) * PERBUF + (t) * TBYTES)
#define BOFF(b, t) ((b) * PERBUF + 2 * TBYTES + (t) * TBYTES)
#define DYN_BYTES (2 * PERBUF + 1024)

__device__ float g_cnt_part[NBLK][NE];
__device__ float g_prob_part[NBLK][NE];
__device__ unsigned int g_sync = 0;   // atomicInc wraps each launch -> graph-replay safe

static __device__ __forceinline__ uint32_t smem_u32(const void* p) {
    uint32_t a;
    asm("{ .reg .u64 t; cvta.to.shared.u64 t, %1; cvt.u32.u64 %0, t; }" : "=r"(a) : "l"(p));
    return a;
}

// baseline-PTX tensor ops (sm_75/80+, valid for plain sm_103 target)
#define LDSM4(r, a) \
    asm volatile("ldmatrix.sync.aligned.m8n8.x4.shared.b16 {%0,%1,%2,%3}, [%4];" \
        : "=r"((r)[0]), "=r"((r)[1]), "=r"((r)[2]), "=r"((r)[3]) : "r"(a))

#define MMA(d, a, b) \
    asm volatile("mma.sync.aligned.m16n8k16.row.col.f32.bf16.bf16.f32 " \
        "{%0,%1,%2,%3}, {%4,%5,%6,%7}, {%8,%9}, {%0,%1,%2,%3};" \
        : "+f"((d)[0]), "+f"((d)[1]), "+f"((d)[2]), "+f"((d)[3]) \
        : "r"((a)[0]), "r"((a)[1]), "r"((a)[2]), "r"((a)[3]), "r"((b)[0]), "r"((b)[1]))

// fp32x4 -> bf16 hi (4) + bf16 lo (4), pairwise cvt (k order preserved)
static __device__ __forceinline__ void split4(float4 v, uint2& hi, uint2& lo) {
    __nv_bfloat162 h0 = __float22bfloat162_rn(make_float2(v.x, v.y));
    __nv_bfloat162 h1 = __float22bfloat162_rn(make_float2(v.z, v.w));
    float2 f0 = __bfloat1622float2(h0);
    float2 f1 = __bfloat1622float2(h1);
    __nv_bfloat162 l0 = __float22bfloat162_rn(make_float2(v.x - f0.x, v.y - f0.y));
    __nv_bfloat162 l1 = __float22bfloat162_rn(make_float2(v.z - f1.x, v.w - f1.y));
    hi.x = *reinterpret_cast<uint32_t*>(&h0);
    hi.y = *reinterpret_cast<uint32_t*>(&h1);
    lo.x = *reinterpret_cast<uint32_t*>(&l0);
    lo.y = *reinterpret_cast<uint32_t*>(&l1);
}

// ---- chunk stages (TM=64: A and B both 64 rows x 16 float4 -> 4 LDG/thread) ----
static __device__ __forceinline__ void ldg_chunk(const float* Hb, const float* W, int c, int tid,
                                                 float4 (&ha)[4], float4 (&wa)[4]) {
    const float* hp = Hb + c * KC;
    const float* wp = W + c * KC;
#pragma unroll
    for (int g = 0; g < 4; g++) {
        int flat = tid + 256 * g, row = flat >> 4, f4 = flat & 15;
        ha[g] = *(const float4*)(hp + (size_t)row * DIM + f4 * 4);
        wa[g] = *(const float4*)(wp + (size_t)row * DIM + f4 * 4);
    }
}
static __device__ __forceinline__ void sts_chunk(char* base, int buf, int tid,
                                                 const float4 (&ha)[4], const float4 (&wa)[4]) {
#pragma unroll
    for (int g = 0; g < 4; g++) {
        int flat = tid + 256 * g, row = flat >> 4, f4 = flat & 15;
        int off = row * APB + f4 * 8;
        uint2 hi, lo;
        split4(ha[g], hi, lo);
        *(uint2*)(base + AOFF(buf, 0) + off) = hi;
        *(uint2*)(base + AOFF(buf, 1) + off) = lo;
        split4(wa[g], hi, lo);
        *(uint2*)(base + BOFF(buf, 0) + off) = hi;
        *(uint2*)(base + BOFF(buf, 1) + off) = lo;
    }
}

// warp tile: m32 (rows (wid&1)*32) x n32 (cols ((wid>>1)&1)*32), k-half (wid>>2).
// Per k16-step: 8 LDSM4 : 24 HMMA (ratio 3). Per-acc term order hh, hl, lh.
static __device__ __forceinline__ void compute_chunk(uint32_t dynb32, int buf, int wid, int lane,
                                                     float (&acc)[2][4][4]) {
    const uint32_t aHi = dynb32 + AOFF(buf, 0), aLo = dynb32 + AOFF(buf, 1);
    const uint32_t bHi = dynb32 + BOFF(buf, 0), bLo = dynb32 + BOFF(buf, 1);
    const int mrow = (wid & 1) * 32;
    const int ncol = ((wid >> 1) & 1) * 32;
    const int kh   = wid >> 2;
    const uint32_t aR0 = (uint32_t)((mrow + (lane & 15)) * APB + (lane >> 4) * 16);
    const uint32_t aR1 = aR0 + (uint32_t)(16 * APB);
    const uint32_t bR0 = (uint32_t)((ncol + (lane & 7) + ((lane >> 4) & 1) * 8) * APB +
                                    ((lane >> 3) & 1) * 16);
#pragma unroll
    for (int ss = 0; ss < 2; ss++) {
        const uint32_t so = (uint32_t)((kh * 2 + ss) * 32);
        uint32_t ah0[4], ah1[4], al0[4], al1[4], bh[2][4], bl[2][4];
        LDSM4(ah0, aHi + aR0 + so);
        LDSM4(ah1, aHi + aR1 + so);
        LDSM4(al0, aLo + aR0 + so);
        LDSM4(al1, aLo + aR1 + so);
        LDSM4(bh[0], bHi + bR0 + so);
        LDSM4(bh[1], bHi + bR0 + (uint32_t)(16 * APB) + so);
        LDSM4(bl[0], bLo + bR0 + so);
        LDSM4(bl[1], bLo + bR0 + (uint32_t)(16 * APB) + so);
        // term-major; same-acc revisit distance 8
#pragma unroll
        for (int jp = 0; jp < 2; jp++) {               // hh
            MMA(acc[0][2 * jp],     ah0, bh[jp]);
            MMA(acc[0][2 * jp + 1], ah0, bh[jp] + 2);
            MMA(acc[1][2 * jp],     ah1, bh[jp]);
            MMA(acc[1][2 * jp + 1], ah1, bh[jp] + 2);
        }
#pragma unroll
        for (int jp = 0; jp < 2; jp++) {               // hl
            MMA(acc[0][2 * jp],     ah0, bl[jp]);
            MMA(acc[0][2 * jp + 1], ah0, bl[jp] + 2);
            MMA(acc[1][2 * jp],     ah1, bl[jp]);
            MMA(acc[1][2 * jp + 1], ah1, bl[jp] + 2);
        }
#pragma unroll
        for (int jp = 0; jp < 2; jp++) {               // lh
            MMA(acc[0][2 * jp],     al0, bh[jp]);
            MMA(acc[0][2 * jp + 1], al0, bh[jp] + 2);
            MMA(acc[1][2 * jp],     al1, bh[jp]);
            MMA(acc[1][2 * jp + 1], al1, bh[jp] + 2);
        }
    }
}

__global__ __launch_bounds__(NT, 2)
void gate_kernel(const float* __restrict__ H, const float* __restrict__ W,
                 float* __restrict__ out, int out_size)
{
    extern __shared__ char dynsm[];
    __shared__ float logits[TM][NE + 1];
    __shared__ float rinv[TM];
    __shared__ float sm_cnt[NE];
    __shared__ float pr[4][NE];
    __shared__ float rc[4][NE], rp[4][NE];
    __shared__ unsigned int is_last;
    __shared__ int fb_cnt;
    __shared__ int fb_list[TM];

    const int tid  = threadIdx.x;
    const int blk  = blockIdx.x;
    const int wid  = tid >> 5;
    const int lane = tid & 31;
    char* base = (char*)((((uintptr_t)dynsm) + 1023) & ~(uintptr_t)1023);
    const uint32_t dynb32 = smem_u32(base);

    if (tid == 0) fb_cnt = 0;
    if (tid < NE) sm_cnt[tid] = 0.f;

    float acc[2][4][4];
#pragma unroll
    for (int m = 0; m < 2; m++)
#pragma unroll
        for (int j = 0; j < 4; j++)
#pragma unroll
            for (int q = 0; q < 4; q++) acc[m][j][q] = 0.f;

    const float* Hb = H + (size_t)blk * TM * DIM;

    // -------- GEMM: 3-term split-bf16 via HMMA, intra-CTA k-split --------
    float4 ha[4], wa[4];
    ldg_chunk(Hb, W, 0, tid, ha, wa);
    sts_chunk(base, 0, tid, ha, wa);
    for (int c = 0; c < NCH; c++) {
        const bool more = (c + 1 < NCH);
        if (more) ldg_chunk(Hb, W, c + 1, tid, ha, wa);
        __syncthreads();
        compute_chunk(dynb32, c & 1, wid, lane, acc);
        if (more) sts_chunk(base, (c + 1) & 1, tid, ha, wa);
    }

    // -------- k-half partials -> logits smem (kh0 writes, kh1 adds) --------
    {
        const int mrow = (wid & 1) * 32;
        const int ncol = ((wid >> 1) & 1) * 32;
        const int kh   = wid >> 2;
        const int r  = lane >> 2;
        const int cb = (lane & 3) * 2;
        if (kh == 0) {
#pragma unroll
            for (int m = 0; m < 2; m++)
#pragma unroll
                for (int j = 0; j < 4; j++) {
                    logits[mrow + m * 16 + r][ncol + cb + j * 8]         = acc[m][j][0];
                    logits[mrow + m * 16 + r][ncol + cb + j * 8 + 1]     = acc[m][j][1];
                    logits[mrow + m * 16 + r + 8][ncol + cb + j * 8]     = acc[m][j][2];
                    logits[mrow + m * 16 + r + 8][ncol + cb + j * 8 + 1] = acc[m][j][3];
                }
        }
        __syncthreads();
        if (kh == 1) {
#pragma unroll
            for (int m = 0; m < 2; m++)
#pragma unroll
                for (int j = 0; j < 4; j++) {
                    logits[mrow + m * 16 + r][ncol + cb + j * 8]         += acc[m][j][0];
                    logits[mrow + m * 16 + r][ncol + cb + j * 8 + 1]     += acc[m][j][1];
                    logits[mrow + m * 16 + r + 8][ncol + cb + j * 8]     += acc[m][j][2];
                    logits[mrow + m * 16 + r + 8][ncol + cb + j * 8 + 1] += acc[m][j][3];
                }
        }
    }
    __syncthreads();

    // -------- near-tie detection: any adjacent gap in top-9 below TAU --------
    if (tid < TM) {
        float v[9];
#pragma unroll
        for (int j = 0; j < 9; j++) v[j] = -1e30f;
        for (int e = 0; e < NE; e++) {
            float nv = logits[tid][e];
#pragma unroll
            for (int j = 0; j < 9; j++) {
                if (nv > v[j]) { float t = v[j]; v[j] = nv; nv = t; }
            }
        }
        float mingap = 1e30f;
#pragma unroll
        for (int j = 0; j < 8; j++) mingap = fminf(mingap, v[j] - v[j + 1]);
        if (mingap < TAU) {
            int ix = atomicAdd(&fb_cnt, 1);
            fb_list[ix] = tid;
        }
    }
    __syncthreads();

    // -------- exact fp32 sequential-k fallback (R0 bit-exact), 4 tokens/pass --------
    {
        const int nfb = fb_cnt;
        for (int f0 = 0; f0 < nfb; f0 += 4) {
            const int fi = f0 + (tid >> 6);
            if (fi < nfb) {
                const int t = fb_list[fi];
                const int e = tid & 63;
                const float* hr = H + (size_t)(blk * TM + t) * DIM;
                const float* wr = W + (size_t)e * DIM;
                float a = 0.f;
                for (int k = 0; k < DIM; k += 4) {
                    float4 hv = *(const float4*)(hr + k);
                    float4 wv = *(const float4*)(wr + k);
                    a = fmaf(hv.x, wv.x, a);
                    a = fmaf(hv.y, wv.y, a);
                    a = fmaf(hv.z, wv.z, a);
                    a = fmaf(hv.w, wv.w, a);
                }
                logits[t][e] = a;
            }
        }
    }
    __syncthreads();

    // -------- per-token softmax + top-8 (proven R0 pipeline) --------
    if (tid < TM) {
        float m = -1e30f;
        for (int e = 0; e < NE; e++) m = fmaxf(m, logits[tid][e]);

        float s = 0.f;
        float val[KTOP]; int idx[KTOP];
#pragma unroll
        for (int j = 0; j < KTOP; j++) { val[j] = -1.f; idx[j] = 0; }
        for (int e = 0; e < NE; e++) {
            float ex = __expf(logits[tid][e] - m);
            logits[tid][e] = ex;   // stash exp for mean-prob pass
            s += ex;
            float nv = ex; int ni = e;
#pragma unroll
            for (int j = 0; j < KTOP; j++) {
                if (nv > val[j]) {
                    float tv = val[j]; val[j] = nv; nv = tv;
                    int   ti = idx[j]; idx[j] = ni; ni = ti;
                }
            }
        }
        rinv[tid] = 1.f / s;

        float ts = 0.f;
#pragma unroll
        for (int j = 0; j < KTOP; j++) ts += val[j];
        const float tinv = 1.f / ts;

        const int gt = blk * TM + tid;
        float* ow = out + (size_t)gt * KTOP;
        float* oi = out + (size_t)NTOK * KTOP + (size_t)gt * KTOP;
#pragma unroll
        for (int j = 0; j < KTOP; j++) {
            ow[j] = val[j] * tinv;
            oi[j] = (float)idx[j];
            atomicAdd(&sm_cnt[idx[j]], 1.f);  // integer counts: order-exact
        }
    }
    __syncthreads();

    // -------- per-block mean-prob partial (4 parts x 16 tokens) --------
    {
        const int e = tid & 63;
        const int p = tid >> 6;
        float sacc = 0.f;
        for (int t = p * 16; t < p * 16 + 16; t++)
            sacc += logits[t][e] * rinv[t];
        pr[p][e] = sacc;
    }
    __syncthreads();
    if (tid < NE) {
        g_prob_part[blk][tid] = pr[0][tid] + pr[1][tid] + pr[2][tid] + pr[3][tid];
        g_cnt_part[blk][tid]  = sm_cnt[tid];
    }

    // -------- last block finalizes the aux loss --------
    __threadfence();
    if (tid == 0)
        is_last = (atomicInc(&g_sync, NBLK - 1) == NBLK - 1);
    __syncthreads();
    if (is_last) {
        const int e = tid & 63;
        const int p = tid >> 6;       // 4 parts x 64 blocks, fixed order
        float c = 0.f, pm = 0.f;
        for (int b = p * 64; b < p * 64 + 64; b++) {
            c  += g_cnt_part[b][e];
            pm += g_prob_part[b][e];
        }
        rc[p][e] = c; rp[p][e] = pm;
        __syncthreads();
        if (tid == 0) {
            float s = 0.f;
            for (int e2 = 0; e2 < NE; e2++) {
                float C = rc[0][e2] + rc[1][e2] + rc[2][e2] + rc[3][e2];
                float P = rp[0][e2] + rp[1][e2] + rp[2][e2] + rp[3][e2];
                s += (C / (float)(NTOK * KTOP)) * (P / (float)NTOK);
            }
            const int pos = NTOK * KTOP * 2;
            if (pos < out_size) out[pos] = ALPHA_C * (float)NE * s;
        }
    }
}

extern "C" void kernel_launch(void* const* d_in, const int* in_sizes, int n_in,
                              void* d_out, int out_size)
{
    const float* H = (const float*)d_in[0];   // hidden_states (16384, 2048) fp32
    const float* W = (const float*)d_in[1];   // weight (64, 2048) fp32
    float* out = (float*)d_out;

    cudaFuncSetAttribute(gate_kernel, cudaFuncAttributeMaxDynamicSharedMemorySize, DYN_BYTES);
    gate_kernel<<<NBLK, NT, DYN_BYTES>>>(H, W, out, out_size);
}

// round 14
// speedup vs baseline: 1.3271x; 1.0360x over previous
#include <cuda_runtime.h>
#include <cuda_bf16.h>
#include <stdint.h>

#define NTOK   16384
#define DIM    2048
#define NE     64
#define KTOP   8
#define ALPHA_C 0.001f

#define TM     64                  // tokens per CTA
#define NT     256                 // 8 warps: 2 m-tiles x 2 n-tiles x 2 k-halves
#define KC     64                  // k per chunk
#define NBLK   (NTOK / TM)         // 256 CTAs -> 2 per SM
#define NCH    (DIM / KC)          // 32 chunks
#define TAU    1e-4f               // near-tie fallback threshold (logit gap)

// smem: bf16 tiles, padded pitch 72 bf16 = 144B (ldmatrix rows -> banks 0,4,..,28)
#define APB    144
#define HTB    9216                // one 64-row tile (hi or lo)
// layout: A buffers (2): [b*18432 + t*9216], then B ring (3): [36864 + b*18432 + t*9216]
#define ABASE(b, t) ((b) * 18432 + (t) * HTB)
#define BBASE(b, t) (36864 + (b) * 18432 + (t) * HTB)
#define DYN_BYTES (92160 + 1024)

__device__ float g_cnt_part[NBLK][NE];
__device__ float g_prob_part[NBLK][NE];
__device__ unsigned int g_sync = 0;   // atomicInc wraps each launch -> graph-replay safe
__device__ __align__(16) __nv_bfloat16 g_Whi[NE * DIM];   // 256 KB
__device__ __align__(16) __nv_bfloat16 g_Wlo[NE * DIM];   // 256 KB

static __device__ __forceinline__ uint32_t smem_u32(const void* p) {
    uint32_t a;
    asm("{ .reg .u64 t; cvta.to.shared.u64 t, %1; cvt.u32.u64 %0, t; }" : "=r"(a) : "l"(p));
    return a;
}

// baseline-PTX tensor / async ops (sm_75/80+, valid for plain sm_103 target)
#define LDSM4(r, a) \
    asm volatile("ldmatrix.sync.aligned.m8n8.x4.shared.b16 {%0,%1,%2,%3}, [%4];" \
        : "=r"((r)[0]), "=r"((r)[1]), "=r"((r)[2]), "=r"((r)[3]) : "r"(a))

#define MMA(d, a, b) \
    asm volatile("mma.sync.aligned.m16n8k16.row.col.f32.bf16.bf16.f32 " \
        "{%0,%1,%2,%3}, {%4,%5,%6,%7}, {%8,%9}, {%0,%1,%2,%3};" \
        : "+f"((d)[0]), "+f"((d)[1]), "+f"((d)[2]), "+f"((d)[3]) \
        : "r"((a)[0]), "r"((a)[1]), "r"((a)[2]), "r"((a)[3]), "r"((b)[0]), "r"((b)[1]))

template <int N> static __device__ __forceinline__ void cp_wait() {
    asm volatile("cp.async.wait_group %0;" :: "n"(N) : "memory");
}

// fp32x4 -> bf16 hi (4) + bf16 lo (4), pairwise cvt (k order preserved)
static __device__ __forceinline__ void split4(float4 v, uint2& hi, uint2& lo) {
    __nv_bfloat162 h0 = __float22bfloat162_rn(make_float2(v.x, v.y));
    __nv_bfloat162 h1 = __float22bfloat162_rn(make_float2(v.z, v.w));
    float2 f0 = __bfloat1622float2(h0);
    float2 f1 = __bfloat1622float2(h1);
    __nv_bfloat162 l0 = __float22bfloat162_rn(make_float2(v.x - f0.x, v.y - f0.y));
    __nv_bfloat162 l1 = __float22bfloat162_rn(make_float2(v.z - f1.x, v.w - f1.y));
    hi.x = *reinterpret_cast<uint32_t*>(&h0);
    hi.y = *reinterpret_cast<uint32_t*>(&h1);
    lo.x = *reinterpret_cast<uint32_t*>(&l0);
    lo.y = *reinterpret_cast<uint32_t*>(&l1);
}

// -------- pre-pass: W fp32 -> bf16 hi/lo (identical split math -> bit-identical tiles) -----
__global__ void wconv_kernel(const float* __restrict__ W)
{
    int i = blockIdx.x * blockDim.x + threadIdx.x;   // over NE*DIM/4 = 32768
    float4 v = ((const float4*)W)[i];
    uint2 hi, lo; split4(v, hi, lo);
    ((uint2*)g_Whi)[i] = hi;
    ((uint2*)g_Wlo)[i] = lo;
}

// ---- gate-kernel chunk stages ----
static __device__ __forceinline__ void ldg_h(const float* Hb, int c, int tid, float4 (&ha)[4]) {
    const float* hp = Hb + c * KC;
#pragma unroll
    for (int g = 0; g < 4; g++) {
        int flat = tid + 256 * g, row = flat >> 4, f4 = flat & 15;
        ha[g] = *(const float4*)(hp + (size_t)row * DIM + f4 * 4);
    }
}
static __device__ __forceinline__ void sts_h(char* base, int buf, int tid, const float4 (&ha)[4]) {
#pragma unroll
    for (int g = 0; g < 4; g++) {
        int flat = tid + 256 * g, row = flat >> 4, f4 = flat & 15;
        int off = row * APB + f4 * 8;
        uint2 hi, lo;
        split4(ha[g], hi, lo);
        *(uint2*)(base + ABASE(buf, 0) + off) = hi;
        *(uint2*)(base + ABASE(buf, 1) + off) = lo;
    }
}
// B tile copy: preconverted bf16 from gmem, 4x cp.async 16B per thread, one commit group.
static __device__ __forceinline__ void b_cpasync(uint32_t dynb32, int c, int bufB, int tid) {
#pragma unroll
    for (int g = 0; g < 4; g++) {
        int flat = tid + 256 * g;
        int arr = flat >> 9, rem = flat & 511, row = rem >> 3, seg = rem & 7;
        const char* src = (const char*)(arr ? g_Wlo : g_Whi) +
                          ((size_t)row * DIM + c * KC) * 2 + seg * 16;
        uint32_t dst = dynb32 + BBASE(bufB, arr) + (uint32_t)(row * APB + seg * 16);
        asm volatile("cp.async.cg.shared.global [%0], [%1], 16;" :: "r"(dst), "l"(src) : "memory");
    }
    asm volatile("cp.async.commit_group;" ::: "memory");
}

// warp tile: m32 (rows (wid&1)*32) x n32 (cols ((wid>>1)&1)*32), k-half (wid>>2).
// Per k16-step: 8 LDSM4 : 24 HMMA. Per-acc term order hh, hl, lh (bit-identical to R13).
static __device__ __forceinline__ void compute_chunk(uint32_t dynb32, int bA, int bB,
                                                     int wid, int lane, float (&acc)[2][4][4]) {
    const uint32_t aHi = dynb32 + ABASE(bA, 0), aLo = dynb32 + ABASE(bA, 1);
    const uint32_t bHi = dynb32 + BBASE(bB, 0), bLo = dynb32 + BBASE(bB, 1);
    const int mrow = (wid & 1) * 32;
    const int ncol = ((wid >> 1) & 1) * 32;
    const int kh   = wid >> 2;
    const uint32_t aR0 = (uint32_t)((mrow + (lane & 15)) * APB + (lane >> 4) * 16);
    const uint32_t aR1 = aR0 + (uint32_t)(16 * APB);
    const uint32_t bR0 = (uint32_t)((ncol + (lane & 7) + ((lane >> 4) & 1) * 8) * APB +
                                    ((lane >> 3) & 1) * 16);
#pragma unroll
    for (int ss = 0; ss < 2; ss++) {
        const uint32_t so = (uint32_t)((kh * 2 + ss) * 32);
        uint32_t ah0[4], ah1[4], al0[4], al1[4], bh[2][4], bl[2][4];
        LDSM4(ah0, aHi + aR0 + so);
        LDSM4(ah1, aHi + aR1 + so);
        LDSM4(al0, aLo + aR0 + so);
        LDSM4(al1, aLo + aR1 + so);
        LDSM4(bh[0], bHi + bR0 + so);
        LDSM4(bh[1], bHi + bR0 + (uint32_t)(16 * APB) + so);
        LDSM4(bl[0], bLo + bR0 + so);
        LDSM4(bl[1], bLo + bR0 + (uint32_t)(16 * APB) + so);
#pragma unroll
        for (int jp = 0; jp < 2; jp++) {               // hh
            MMA(acc[0][2 * jp],     ah0, bh[jp]);
            MMA(acc[0][2 * jp + 1], ah0, bh[jp] + 2);
            MMA(acc[1][2 * jp],     ah1, bh[jp]);
            MMA(acc[1][2 * jp + 1], ah1, bh[jp] + 2);
        }
#pragma unroll
        for (int jp = 0; jp < 2; jp++) {               // hl
            MMA(acc[0][2 * jp],     ah0, bl[jp]);
            MMA(acc[0][2 * jp + 1], ah0, bl[jp] + 2);
            MMA(acc[1][2 * jp],     ah1, bl[jp]);
            MMA(acc[1][2 * jp + 1], ah1, bl[jp] + 2);
        }
#pragma unroll
        for (int jp = 0; jp < 2; jp++) {               // lh
            MMA(acc[0][2 * jp],     al0, bh[jp]);
            MMA(acc[0][2 * jp + 1], al0, bh[jp] + 2);
            MMA(acc[1][2 * jp],     al1, bh[jp]);
            MMA(acc[1][2 * jp + 1], al1, bh[jp] + 2);
        }
    }
}

__global__ __launch_bounds__(NT, 2)
void gate_kernel(const float* __restrict__ H, const float* __restrict__ W,
                 float* __restrict__ out, int out_size)
{
    extern __shared__ char dynsm[];
    __shared__ float rinv[TM];
    __shared__ float sm_cnt[NE];
    __shared__ float pr[4][NE];
    __shared__ float rc[4][NE], rp[4][NE];
    __shared__ unsigned int is_last;
    __shared__ int fb_cnt;
    __shared__ int fb_list[TM];

    const int tid  = threadIdx.x;
    const int blk  = blockIdx.x;
    const int wid  = tid >> 5;
    const int lane = tid & 31;
    char* base = (char*)((((uintptr_t)dynsm) + 1023) & ~(uintptr_t)1023);
    const uint32_t dynb32 = smem_u32(base);

    if (tid == 0) fb_cnt = 0;
    if (tid < NE) sm_cnt[tid] = 0.f;

    float acc[2][4][4];
#pragma unroll
    for (int m = 0; m < 2; m++)
#pragma unroll
        for (int j = 0; j < 4; j++)
#pragma unroll
            for (int q = 0; q < 4; q++) acc[m][j][q] = 0.f;

    const float* Hb = H + (size_t)blk * TM * DIM;

    // -------- GEMM: 3-term split-bf16 via HMMA; B via cp.async distance-2 ring --------
    float4 ha[4];
    b_cpasync(dynb32, 0, 0, tid);          // group: chunk0 -> B ring 0
    b_cpasync(dynb32, 1, 1, tid);          // group: chunk1 -> B ring 1
    ldg_h(Hb, 0, tid, ha);
    sts_h(base, 0, tid, ha);
    for (int c = 0; c < NCH; c++) {
        const int bA = c & 1;
        const int bB = c % 3;
        const bool more = (c + 1 < NCH);
        if (more) { ldg_h(Hb, c + 1, tid, ha); cp_wait<1>(); }
        else      { cp_wait<0>(); }
        __syncthreads();                   // chunk c tiles (H sts + B cp.async) visible; prior compute done
        compute_chunk(dynb32, bA, bB, wid, lane, acc);
        if (more) sts_h(base, bA ^ 1, tid, ha);
        // B ring slot (c+2)%3 == (c-1)%3: last read at compute(c-1), done by all threads
        // (everyone passed this iteration's barrier).
        if (c + 2 < NCH) b_cpasync(dynb32, c + 2, (c + 2) % 3, tid);
    }
    __syncthreads();   // all compute done; GEMM buffers dead -> reuse as logits

    float (*logits)[NE + 1] = (float(*)[NE + 1])base;

    // -------- k-half partials -> logits smem (kh0 writes, kh1 adds) --------
    {
        const int mrow = (wid & 1) * 32;
        const int ncol = ((wid >> 1) & 1) * 32;
        const int kh   = wid >> 2;
        const int r  = lane >> 2;
        const int cb = (lane & 3) * 2;
        if (kh == 0) {
#pragma unroll
            for (int m = 0; m < 2; m++)
#pragma unroll
                for (int j = 0; j < 4; j++) {
                    logits[mrow + m * 16 + r][ncol + cb + j * 8]         = acc[m][j][0];
                    logits[mrow + m * 16 + r][ncol + cb + j * 8 + 1]     = acc[m][j][1];
                    logits[mrow + m * 16 + r + 8][ncol + cb + j * 8]     = acc[m][j][2];
                    logits[mrow + m * 16 + r + 8][ncol + cb + j * 8 + 1] = acc[m][j][3];
                }
        }
        __syncthreads();
        if (kh == 1) {
#pragma unroll
            for (int m = 0; m < 2; m++)
#pragma unroll
                for (int j = 0; j < 4; j++) {
                    logits[mrow + m * 16 + r][ncol + cb + j * 8]         += acc[m][j][0];
                    logits[mrow + m * 16 + r][ncol + cb + j * 8 + 1]     += acc[m][j][1];
                    logits[mrow + m * 16 + r + 8][ncol + cb + j * 8]     += acc[m][j][2];
                    logits[mrow + m * 16 + r + 8][ncol + cb + j * 8 + 1] += acc[m][j][3];
                }
        }
    }
    __syncthreads();

    // -------- near-tie detection: any adjacent gap in top-9 below TAU --------
    if (tid < TM) {
        float v[9];
#pragma unroll
        for (int j = 0; j < 9; j++) v[j] = -1e30f;
        for (int e = 0; e < NE; e++) {
            float nv = logits[tid][e];
#pragma unroll
            for (int j = 0; j < 9; j++) {
                if (nv > v[j]) { float t = v[j]; v[j] = nv; nv = t; }
            }
        }
        float mingap = 1e30f;
#pragma unroll
        for (int j = 0; j < 8; j++) mingap = fminf(mingap, v[j] - v[j + 1]);
        if (mingap < TAU) {
            int ix = atomicAdd(&fb_cnt, 1);
            fb_list[ix] = tid;
        }
    }
    __syncthreads();

    // -------- exact fp32 sequential-k fallback (R0 bit-exact), 4 tokens/pass --------
    {
        const int nfb = fb_cnt;
        for (int f0 = 0; f0 < nfb; f0 += 4) {
            const int fi = f0 + (tid >> 6);
            if (fi < nfb) {
                const int t = fb_list[fi];
                const int e = tid & 63;
                const float* hr = H + (size_t)(blk * TM + t) * DIM;
                const float* wr = W + (size_t)e * DIM;
                float a = 0.f;
                for (int k = 0; k < DIM; k += 4) {
                    float4 hv = *(const float4*)(hr + k);
                    float4 wv = *(const float4*)(wr + k);
                    a = fmaf(hv.x, wv.x, a);
                    a = fmaf(hv.y, wv.y, a);
                    a = fmaf(hv.z, wv.z, a);
                    a = fmaf(hv.w, wv.w, a);
                }
                logits[t][e] = a;
            }
        }
    }
    __syncthreads();

    // -------- per-token softmax + top-8 (proven R0 pipeline) --------
    if (tid < TM) {
        float m = -1e30f;
        for (int e = 0; e < NE; e++) m = fmaxf(m, logits[tid][e]);

        float s = 0.f;
        float val[KTOP]; int idx[KTOP];
#pragma unroll
        for (int j = 0; j < KTOP; j++) { val[j] = -1.f; idx[j] = 0; }
        for (int e = 0; e < NE; e++) {
            float ex = __expf(logits[tid][e] - m);
            logits[tid][e] = ex;   // stash exp for mean-prob pass
            s += ex;
            float nv = ex; int ni = e;
#pragma unroll
            for (int j = 0; j < KTOP; j++) {
                if (nv > val[j]) {
                    float tv = val[j]; val[j] = nv; nv = tv;
                    int   ti = idx[j]; idx[j] = ni; ni = ti;
                }
            }
        }
        rinv[tid] = 1.f / s;

        float ts = 0.f;
#pragma unroll
        for (int j = 0; j < KTOP; j++) ts += val[j];
        const float tinv = 1.f / ts;

        const int gt = blk * TM + tid;
        float* ow = out + (size_t)gt * KTOP;
        float* oi = out + (size_t)NTOK * KTOP + (size_t)gt * KTOP;
#pragma unroll
        for (int j = 0; j < KTOP; j++) {
            ow[j] = val[j] * tinv;
            oi[j] = (float)idx[j];
            atomicAdd(&sm_cnt[idx[j]], 1.f);  // integer counts: order-exact
        }
    }
    __syncthreads();

    // -------- per-block mean-prob partial (4 parts x 16 tokens) --------
    {
        const int e = tid & 63;
        const int p = tid >> 6;
        float sacc = 0.f;
        for (int t = p * 16; t < p * 16 + 16; t++)
            sacc += logits[t][e] * rinv[t];
        pr[p][e] = sacc;
    }
    __syncthreads();
    if (tid < NE) {
        g_prob_part[blk][tid] = pr[0][tid] + pr[1][tid] + pr[2][tid] + pr[3][tid];
        g_cnt_part[blk][tid]  = sm_cnt[tid];
    }

    // -------- last block finalizes the aux loss --------
    __threadfence();
    if (tid == 0)
        is_last = (atomicInc(&g_sync, NBLK - 1) == NBLK - 1);
    __syncthreads();
    if (is_last) {
        const int e = tid & 63;
        const int p = tid >> 6;       // 4 parts x 64 blocks, fixed order
        float c = 0.f, pm = 0.f;
        for (int b = p * 64; b < p * 64 + 64; b++) {
            c  += g_cnt_part[b][e];
            pm += g_prob_part[b][e];
        }
        rc[p][e] = c; rp[p][e] = pm;
        __syncthreads();
        if (tid == 0) {
            float s = 0.f;
            for (int e2 = 0; e2 < NE; e2++) {
                float C = rc[0][e2] + rc[1][e2] + rc[2][e2] + rc[3][e2];
                float P = rp[0][e2] + rp[1][e2] + rp[2][e2] + rp[3][e2];
                s += (C / (float)(NTOK * KTOP)) * (P / (float)NTOK);
            }
            const int pos = NTOK * KTOP * 2;
            if (pos < out_size) out[pos] = ALPHA_C * (float)NE * s;
        }
    }
}

extern "C" void kernel_launch(void* const* d_in, const int* in_sizes, int n_in,
                              void* d_out, int out_size)
{
    const float* H = (const float*)d_in[0];   // hidden_states (16384, 2048) fp32
    const float* W = (const float*)d_in[1];   // weight (64, 2048) fp32
    float* out = (float*)d_out;

    wconv_kernel<<<NE * DIM / 4 / 256, 256>>>(W);
    cudaFuncSetAttribute(gate_kernel, cudaFuncAttributeMaxDynamicSharedMemorySize, DYN_BYTES);
    gate_kernel<<<NBLK, NT, DYN_BYTES>>>(H, W, out, out_size);
}